// round 2
// baseline (speedup 1.0000x reference)
#include <cuda_runtime.h>

// Problem constants: N = M = 8192 points, 4 components each.
#define SPLITS 16
#define CHUNK 512            // ori points per split (8192 / 16)
#define ADV_PER_BLOCK 1024
#define THREADS 256
#define T 4                  // adv points per thread

// Graph-safe scratch: fully overwritten every launch, no init required.
__device__ float g_partial[SPLITS * 8192];
__device__ float g_blockmax[64];

// Kernel 1: for each (adv block, ori split), compute per-adv-point min of
// sqdist = a2 + (b2 + dot(-2a, b)) over the split's ori chunk.
__global__ __launch_bounds__(THREADS)
void hd_partial_min(const float* __restrict__ adv, const float* __restrict__ ori,
                    int n, int m) {
    __shared__ float4 sb[CHUNK];   // scaled ori point
    __shared__ float  sc[CHUNK];   // |scaled ori|^2

    const int tid = threadIdx.x;
    const int j0  = blockIdx.y * CHUNK;
    const int jn  = min(CHUNK, m - j0);

    // Stage ori chunk into shared memory (coalesced float4 loads).
    for (int j = tid; j < jn; j += THREADS) {
        float4 b = reinterpret_cast<const float4*>(ori)[j0 + j];
        b.w *= 0.5f;   // INTENSITY_WEIGHT
        sb[j] = b;
        sc[j] = b.x * b.x + b.y * b.y + b.z * b.z + b.w * b.w;
    }
    __syncthreads();

    // Each thread owns T adv points (strided by THREADS for coalescing).
    float ax[T], ay[T], az[T], aw[T], a2[T], mn[T];
    const int base = blockIdx.x * ADV_PER_BLOCK + tid;
#pragma unroll
    for (int k = 0; k < T; k++) {
        const int i = base + k * THREADS;
        float4 a = reinterpret_cast<const float4*>(adv)[i];
        a.w *= 0.5f;
        a2[k] = a.x * a.x + a.y * a.y + a.z * a.z + a.w * a.w;
        ax[k] = -2.0f * a.x;
        ay[k] = -2.0f * a.y;
        az[k] = -2.0f * a.z;
        aw[k] = -2.0f * a.w;
        mn[k] = INFINITY;
    }

    // Mainloop: 4 FFMA + 1 FMNMX per distance; smem reads broadcast across warp.
#pragma unroll 4
    for (int j = 0; j < jn; j++) {
        const float4 b = sb[j];
        const float  c = sc[j];
#pragma unroll
        for (int k = 0; k < T; k++) {
            float t = fmaf(ax[k], b.x, c);
            t = fmaf(ay[k], b.y, t);
            t = fmaf(az[k], b.z, t);
            t = fmaf(aw[k], b.w, t);
            mn[k] = fminf(mn[k], t);
        }
    }

#pragma unroll
    for (int k = 0; k < T; k++) {
        g_partial[blockIdx.y * n + base + k * THREADS] = mn[k] + a2[k];
    }
}

// Kernel 2: combine splits (min) per adv point, then block-level max.
// Grid: n/128 = 64 blocks of 128 threads.
__global__ __launch_bounds__(128)
void hd_combine(int n) {
    const int i = blockIdx.x * 128 + threadIdx.x;
    float v = INFINITY;
#pragma unroll
    for (int s = 0; s < SPLITS; s++) {
        v = fminf(v, g_partial[s * n + i]);
    }
    __shared__ float sm[128];
    sm[threadIdx.x] = v;
    __syncthreads();
    for (int off = 64; off > 0; off >>= 1) {
        if (threadIdx.x < off)
            sm[threadIdx.x] = fmaxf(sm[threadIdx.x], sm[threadIdx.x + off]);
        __syncthreads();
    }
    if (threadIdx.x == 0) g_blockmax[blockIdx.x] = sm[0];
}

// Kernel 3: reduce 64 block maxima -> out[0]. One warp.
__global__ void hd_final(float* __restrict__ out) {
    float v = fmaxf(g_blockmax[threadIdx.x], g_blockmax[threadIdx.x + 32]);
#pragma unroll
    for (int off = 16; off > 0; off >>= 1) {
        v = fmaxf(v, __shfl_xor_sync(0xffffffffu, v, off));
    }
    if (threadIdx.x == 0) out[0] = v;   // LOSS_WEIGHT = 1.0
}

extern "C" void kernel_launch(void* const* d_in, const int* in_sizes, int n_in,
                              void* d_out, int out_size) {
    const float* adv = (const float*)d_in[0];
    const float* ori = (const float*)d_in[1];
    float* out = (float*)d_out;

    const int n = in_sizes[0] / 4;   // 8192
    const int m = in_sizes[1] / 4;   // 8192

    dim3 grid1((n + ADV_PER_BLOCK - 1) / ADV_PER_BLOCK, SPLITS);
    hd_partial_min<<<grid1, THREADS>>>(adv, ori, n, m);
    hd_combine<<<n / 128, 128>>>(n);
    hd_final<<<1, 32>>>(out);
}

// round 3
// speedup vs baseline: 1.0926x; 1.0926x over previous
#include <cuda_runtime.h>
#include <cstdint>

// N = M = 8192 points, 4 components. Grid: 8 adv-blocks x 37 splits = 296 CTAs
// = exactly 2 CTAs per SM on 148 SMs.
#define SPLITS 37
#define CHUNK 222            // per-split ori points (jn is 222 or 200 -> always even)
#define ADV_PER_BLOCK 1024
#define THREADS 256
#define T 4                  // adv points per thread
#define NMAX 8192

// Graph-safe scratch: fully overwritten every launch.
__device__ float g_partial[SPLITS * NMAX];
__device__ float g_blockmax[64];

// Struct-of-pairs ori layout: one LDS.128 -> {bx0,bx1,by0,by1} which reinterprets
// directly as two packed f32x2 operands with zero mov overhead.
struct __align__(16) OriPair {
    float f[12];  // bx0 bx1 | by0 by1 | bz0 bz1 | bw0 bw1 | c0 c1 | pad pad
};

__device__ __forceinline__ uint64_t ffma2(uint64_t a, uint64_t b, uint64_t c) {
    uint64_t d;
    asm("fma.rn.f32x2 %0, %1, %2, %3;" : "=l"(d) : "l"(a), "l"(b), "l"(c));
    return d;
}
__device__ __forceinline__ uint64_t pack2(float x) {
    uint64_t d;
    asm("mov.b64 %0, {%1, %1};" : "=l"(d) : "f"(x));
    return d;
}
__device__ __forceinline__ float2 unpack2(uint64_t v) {
    float2 r;
    asm("mov.b64 {%0, %1}, %2;" : "=f"(r.x), "=f"(r.y) : "l"(v));
    return r;
}

__global__ __launch_bounds__(THREADS)
void hd_partial_min(const float* __restrict__ adv, const float* __restrict__ ori,
                    int n, int m) {
    __shared__ OriPair sp[(CHUNK + 1) / 2];

    const int tid = threadIdx.x;
    const int j0  = blockIdx.y * CHUNK;
    const int jn  = min(CHUNK, m - j0);

    // Stage ori chunk into pair layout.
    for (int j = tid; j < jn; j += THREADS) {
        float4 b = reinterpret_cast<const float4*>(ori)[j0 + j];
        b.w *= 0.5f;  // INTENSITY_WEIGHT
        float c = b.x * b.x + b.y * b.y + b.z * b.z + b.w * b.w;
        float* dst = sp[j >> 1].f + (j & 1);
        dst[0] = b.x; dst[2] = b.y; dst[4] = b.z; dst[6] = b.w; dst[8] = c;
    }
    __syncthreads();

    uint64_t ax[T], ay[T], az[T], aw[T];
    float a2[T], mn[T];
    const int base = blockIdx.x * ADV_PER_BLOCK + tid;
#pragma unroll
    for (int k = 0; k < T; k++) {
        float4 a = reinterpret_cast<const float4*>(adv)[base + k * THREADS];
        a.w *= 0.5f;
        a2[k] = a.x * a.x + a.y * a.y + a.z * a.z + a.w * a.w;
        ax[k] = pack2(-2.0f * a.x);
        ay[k] = pack2(-2.0f * a.y);
        az[k] = pack2(-2.0f * a.z);
        aw[k] = pack2(-2.0f * a.w);
        mn[k] = INFINITY;
    }

    // Mainloop: per pair of ori points, per adv point: 4 FFMA2 + 2 FMNMX.
    const int np = jn >> 1;
#pragma unroll 2
    for (int p = 0; p < np; p++) {
        const ulonglong2 q0 = *reinterpret_cast<const ulonglong2*>(&sp[p].f[0]);
        const ulonglong2 q1 = *reinterpret_cast<const ulonglong2*>(&sp[p].f[4]);
        const uint64_t   cc = *reinterpret_cast<const uint64_t*>(&sp[p].f[8]);
#pragma unroll
        for (int k = 0; k < T; k++) {
            uint64_t d = ffma2(ax[k], q0.x, cc);
            d = ffma2(ay[k], q0.y, d);
            d = ffma2(az[k], q1.x, d);
            d = ffma2(aw[k], q1.y, d);
            float2 t = unpack2(d);
            mn[k] = fminf(mn[k], fminf(t.x, t.y));  // pairwise min independent of mn chain
        }
    }
    // Odd-tail guard (never taken for these shapes: jn is 222 or 200).
    if (jn & 1) {
        const float* f = sp[(jn - 1) >> 1].f;
        const float bx = f[0], by = f[2], bz = f[4], bw = f[6], c = f[8];
#pragma unroll
        for (int k = 0; k < T; k++) {
            float t = fmaf(unpack2(ax[k]).x, bx, c);
            t = fmaf(unpack2(ay[k]).x, by, t);
            t = fmaf(unpack2(az[k]).x, bz, t);
            t = fmaf(unpack2(aw[k]).x, bw, t);
            mn[k] = fminf(mn[k], t);
        }
    }

#pragma unroll
    for (int k = 0; k < T; k++) {
        g_partial[blockIdx.y * n + base + k * THREADS] = mn[k] + a2[k];
    }
}

// Kernel 2: combine splits (min) per adv point, then block-level max.
__global__ __launch_bounds__(128)
void hd_combine(int n) {
    const int i = blockIdx.x * 128 + threadIdx.x;
    float v = INFINITY;
#pragma unroll
    for (int s = 0; s < SPLITS; s++) {
        v = fminf(v, g_partial[s * n + i]);
    }
    __shared__ float sm[128];
    sm[threadIdx.x] = v;
    __syncthreads();
    for (int off = 64; off > 0; off >>= 1) {
        if (threadIdx.x < off)
            sm[threadIdx.x] = fmaxf(sm[threadIdx.x], sm[threadIdx.x + off]);
        __syncthreads();
    }
    if (threadIdx.x == 0) g_blockmax[blockIdx.x] = sm[0];
}

// Kernel 3: reduce 64 block maxima -> out[0]. One warp.
__global__ void hd_final(float* __restrict__ out) {
    float v = fmaxf(g_blockmax[threadIdx.x], g_blockmax[threadIdx.x + 32]);
#pragma unroll
    for (int off = 16; off > 0; off >>= 1) {
        v = fmaxf(v, __shfl_xor_sync(0xffffffffu, v, off));
    }
    if (threadIdx.x == 0) out[0] = v;   // LOSS_WEIGHT = 1.0
}

extern "C" void kernel_launch(void* const* d_in, const int* in_sizes, int n_in,
                              void* d_out, int out_size) {
    const float* adv = (const float*)d_in[0];
    const float* ori = (const float*)d_in[1];
    float* out = (float*)d_out;

    const int n = in_sizes[0] / 4;   // 8192
    const int m = in_sizes[1] / 4;   // 8192

    dim3 grid1((n + ADV_PER_BLOCK - 1) / ADV_PER_BLOCK, SPLITS);
    hd_partial_min<<<grid1, THREADS>>>(adv, ori, n, m);
    hd_combine<<<n / 128, 128>>>(n);
    hd_final<<<1, 32>>>(out);
}